// round 5
// baseline (speedup 1.0000x reference)
#include <cuda_runtime.h>

// Problem constants
constexpr int Bc   = 256;
constexpr int Tc   = 50;
constexpr int Nn   = 32;
constexpr int FINc = 16;
constexpr int HGc  = 64;
constexpr int HFCc = 128;
constexpr int G3c  = 384;           // 3*HFC
constexpr int BT   = Bc * Tc;       // 12800
constexpr int OSTc = 8;

// Scratch (static __device__ globals: allocation-free rule)
__device__ float g_graph[BT * HGc];          // graph_seq (B*T, 64)
__device__ float g_xp[3][BT * G3c];          // x@Wi+bi per stream
__device__ float g_concat[BT * G3c];         // [gG | gS | gT]

// ---------------------------------------------------------------------------
// Kernel 1: GNN (2 layers, layer 2 only node 0) — one block per (b,t)
// ---------------------------------------------------------------------------
__global__ void k_gnn(const float* __restrict__ feat, const int* __restrict__ adj,
                      const float* __restrict__ W1, const float* __restrict__ b1,
                      const float* __restrict__ W3, const float* __restrict__ b3,
                      const float* __restrict__ lg, const float* __restrict__ lb)
{
    __shared__ float s_feat[Nn * FINc];
    __shared__ int   s_adj[Nn * Nn];
    __shared__ float s_deg[Nn];
    __shared__ float s_agg[Nn * FINc];
    __shared__ float s_pre[Nn * HGc];
    __shared__ float s_W1[FINc * HGc];
    __shared__ float s_W3[HGc * HGc];
    __shared__ float s_agg2[HGc];
    __shared__ float s_pre2[HGc];

    const int bt = blockIdx.x;
    const int t  = threadIdx.x;          // 128 threads

    for (int i = t; i < Nn * FINc; i += 128) s_feat[i] = feat[(size_t)bt * Nn * FINc + i];
    for (int i = t; i < Nn * Nn;   i += 128) s_adj[i]  = adj[(size_t)bt * Nn * Nn + i];
    for (int i = t; i < FINc * HGc; i += 128) s_W1[i]  = W1[i];
    for (int i = t; i < HGc * HGc;  i += 128) s_W3[i]  = W3[i];
    __syncthreads();

    if (t < Nn) {                        // deg = sum(adj) + 1 (self loop)
        float s = 1.0f;
        #pragma unroll 8
        for (int j = 0; j < Nn; j++) s += (float)s_adj[t * Nn + j];
        s_deg[t] = s;
    }
    __syncthreads();

    // agg1[i][f] = (feat[i][f] + sum_j adj[i][j]*feat[j][f]) / deg[i]
    for (int idx = t; idx < Nn * FINc; idx += 128) {
        int i = idx >> 4, f = idx & 15;
        float acc = s_feat[i * FINc + f];
        #pragma unroll 8
        for (int j = 0; j < Nn; j++)
            acc += (float)s_adj[i * Nn + j] * s_feat[j * FINc + f];
        s_agg[idx] = acc / s_deg[i];
    }
    __syncthreads();

    // pre1 = agg1 @ W1 + b1
    for (int idx = t; idx < Nn * HGc; idx += 128) {
        int i = idx >> 6, h = idx & 63;
        float acc = b1[h];
        #pragma unroll
        for (int k = 0; k < FINc; k++)
            acc += s_agg[i * FINc + k] * s_W1[k * HGc + h];
        s_pre[idx] = acc;
    }
    __syncthreads();

    // LN(64) + relu per node row -> h1 (in-place)
    {
        int w = t >> 5, lane = t & 31;
        float g0 = lg[lane], g1 = lg[lane + 32];
        float c0 = lb[lane], c1 = lb[lane + 32];
        for (int row = w; row < Nn; row += 4) {
            float x0 = s_pre[row * HGc + lane];
            float x1 = s_pre[row * HGc + 32 + lane];
            float s = x0 + x1, q = x0 * x0 + x1 * x1;
            #pragma unroll
            for (int o = 16; o; o >>= 1) {
                s += __shfl_xor_sync(0xffffffffu, s, o);
                q += __shfl_xor_sync(0xffffffffu, q, o);
            }
            float m = s * (1.0f / 64.0f);
            float v = q * (1.0f / 64.0f) - m * m;
            float inv = rsqrtf(v + 1e-5f);
            s_pre[row * HGc + lane]      = fmaxf((x0 - m) * inv * g0 + c0, 0.f);
            s_pre[row * HGc + 32 + lane] = fmaxf((x1 - m) * inv * g1 + c1, 0.f);
        }
    }
    __syncthreads();

    // layer 2, row 0 only: agg2[f]
    if (t < HGc) {
        float acc = s_pre[t];            // identity j==0
        #pragma unroll 8
        for (int j = 0; j < Nn; j++)
            acc += (float)s_adj[j] * s_pre[j * HGc + t];
        s_agg2[t] = acc / s_deg[0];
    }
    __syncthreads();

    if (t < HGc) {
        float acc = b3[t];
        #pragma unroll 16
        for (int k = 0; k < HGc; k++)
            acc += s_agg2[k] * s_W3[k * HGc + t];
        s_pre2[t] = acc;
    }
    __syncthreads();

    if (t < 32) {
        float x0 = s_pre2[t], x1 = s_pre2[t + 32];
        float s = x0 + x1, q = x0 * x0 + x1 * x1;
        #pragma unroll
        for (int o = 16; o; o >>= 1) {
            s += __shfl_xor_sync(0xffffffffu, s, o);
            q += __shfl_xor_sync(0xffffffffu, q, o);
        }
        float m = s * (1.f / 64.f);
        float v = q * (1.f / 64.f) - m * m;
        float inv = rsqrtf(v + 1e-5f);
        g_graph[(size_t)bt * HGc + t]      = fmaxf((x0 - m) * inv * lg[t] + lb[t], 0.f);
        g_graph[(size_t)bt * HGc + t + 32] = fmaxf((x1 - m) * inv * lg[t + 32] + lb[t + 32], 0.f);
    }
}

// ---------------------------------------------------------------------------
// Kernel 2: xp = x @ Wi + bi for the three GRU streams (tiled GEMM)
// grid (400 rowTiles, 3 colTiles, 3 streams), 256 threads, 32x128 tile
// ---------------------------------------------------------------------------
__global__ void k_xp(const float* __restrict__ sensor, const float* __restrict__ target,
                     const float* __restrict__ WiG, const float* __restrict__ biG,
                     const float* __restrict__ WiS, const float* __restrict__ biS,
                     const float* __restrict__ WiT, const float* __restrict__ biT)
{
    __shared__ float sA[32 * 64];
    __shared__ float sW[64 * 128];

    const int s    = blockIdx.z;
    const int col0 = blockIdx.y * 128;
    const int row0 = blockIdx.x * 32;
    const int t    = threadIdx.x;        // 256

    const float* A; const float* Wi; const float* bi; int K;
    if (s == 0)      { A = g_graph; Wi = WiG; bi = biG; K = 64; }
    else if (s == 1) { A = sensor;  Wi = WiS; bi = biS; K = 32; }
    else             { A = target;  Wi = WiT; bi = biT; K = 32; }

    for (int i = t; i < 32 * K; i += 256) {
        int r = i / K, k = i % K;
        sA[r * K + k] = A[(size_t)(row0 + r) * K + k];
    }
    for (int i = t; i < K * 128; i += 256) {
        int k = i >> 7, c = i & 127;
        sW[i] = Wi[(size_t)k * G3c + col0 + c];
    }
    __syncthreads();

    const int tc = t & 31, tr = t >> 5;  // 8 row-threads x 32 col-threads
    float acc[4][4];
    #pragma unroll
    for (int b = 0; b < 4; b++) {
        float bv = bi[col0 + tc + 32 * b];
        #pragma unroll
        for (int a = 0; a < 4; a++) acc[a][b] = bv;
    }
    for (int k = 0; k < K; k++) {
        float av[4], wv[4];
        #pragma unroll
        for (int a = 0; a < 4; a++) av[a] = sA[(tr + 8 * a) * K + k];
        #pragma unroll
        for (int b = 0; b < 4; b++) wv[b] = sW[k * 128 + tc + 32 * b];
        #pragma unroll
        for (int a = 0; a < 4; a++)
            #pragma unroll
            for (int b = 0; b < 4; b++)
                acc[a][b] = fmaf(av[a], wv[b], acc[a][b]);
    }
    float* Xp = g_xp[s];
    #pragma unroll
    for (int a = 0; a < 4; a++)
        #pragma unroll
        for (int b = 0; b < 4; b++)
            Xp[(size_t)(row0 + tr + 8 * a) * G3c + col0 + tc + 32 * b] = acc[a][b];
}

// ---------------------------------------------------------------------------
// Kernel 3: persistent GRU recurrence. 96 blocks (3 streams x 32 batch chunks),
// 384 threads; thread j owns gh column j with its Wh column packed in 64 f32x2
// registers; fma.rn.f32x2 gives 2 MACs/instr.
// ---------------------------------------------------------------------------
__device__ __forceinline__ unsigned long long pk2(float lo, float hi) {
    unsigned long long r;
    asm("mov.b64 %0, {%1,%2};" : "=l"(r) : "f"(lo), "f"(hi));
    return r;
}
__device__ __forceinline__ unsigned long long ffma2(unsigned long long a,
                                                    unsigned long long b,
                                                    unsigned long long c) {
    unsigned long long d;
    asm("fma.rn.f32x2 %0, %1, %2, %3;" : "=l"(d) : "l"(a), "l"(b), "l"(c));
    return d;
}
__device__ __forceinline__ float f2red(unsigned long long a) {
    float lo, hi;
    asm("mov.b64 {%0,%1}, %2;" : "=f"(lo), "=f"(hi) : "l"(a));
    return lo + hi;
}

__global__ void __launch_bounds__(384, 1)
k_gru(const float* __restrict__ WhG, const float* __restrict__ bhG,
      const float* __restrict__ WhS, const float* __restrict__ bhS,
      const float* __restrict__ WhT, const float* __restrict__ bhT)
{
    __shared__ __align__(16) float sh[8][128];   // hidden state, 8 batch rows
    __shared__ float sAg[8][384];                // pre_r | pre_z | hg
    __shared__ float sIG[8][128];                // ig (input part of n gate)

    const int bx     = blockIdx.x;
    const int stream = bx >> 5;                  // 0..2
    const int row0   = (bx & 31) * 8;            // batch rows [row0, row0+8)
    const int j      = threadIdx.x;              // 0..383 column owner

    const float* Wh; const float* bh;
    if (stream == 0)      { Wh = WhG; bh = bhG; }
    else if (stream == 1) { Wh = WhS; bh = bhS; }
    else                  { Wh = WhT; bh = bhT; }
    const float* Xp     = g_xp[stream];
    const int    outOff = stream * 128;

    // Preload this thread's Wh column as 64 packed f32x2 registers
    unsigned long long whp[64];
    #pragma unroll
    for (int kk = 0; kk < 64; kk++) {
        float lo = Wh[(size_t)(2 * kk) * G3c + j];
        float hi = Wh[(size_t)(2 * kk + 1) * G3c + j];
        whp[kk] = pk2(lo, hi);
    }
    const float bhj = bh[j];

    for (int i = j; i < 8 * 128; i += 384) sh[i >> 7][i & 127] = 0.f;
    __syncthreads();

    for (int tstep = 0; tstep < Tc; tstep++) {
        float xv[8], ghv[8];
        #pragma unroll
        for (int r = 0; r < 8; r++)
            xv[r] = Xp[((size_t)(row0 + r) * Tc + tstep) * G3c + j];

        #pragma unroll
        for (int r = 0; r < 8; r++) {
            unsigned long long a0 = 0ull, a1 = 0ull;
            #pragma unroll
            for (int q = 0; q < 32; q++) {
                ulonglong2 hv = *reinterpret_cast<const ulonglong2*>(&sh[r][4 * q]);
                a0 = ffma2(hv.x, whp[2 * q],     a0);
                a1 = ffma2(hv.y, whp[2 * q + 1], a1);
            }
            ghv[r] = f2red(a0) + f2red(a1) + bhj;
        }

        if (j < 256) {
            #pragma unroll
            for (int r = 0; r < 8; r++) sAg[r][j] = xv[r] + ghv[r];
        } else {
            #pragma unroll
            for (int r = 0; r < 8; r++) { sAg[r][j] = ghv[r]; sIG[r][j - 256] = xv[r]; }
        }
        __syncthreads();

        // gate math: 1024 (row, unit) pairs over 384 threads
        for (int u = j; u < 8 * 128; u += 384) {
            int r = u >> 7, m = u & 127;
            float pr = sAg[r][m];
            float pz = sAg[r][128 + m];
            float hg = sAg[r][256 + m];
            float ig = sIG[r][m];
            float rr = 1.f / (1.f + __expf(-pr));
            float zz = 1.f / (1.f + __expf(-pz));
            float nn = tanhf(fmaf(rr, hg, ig));
            float hn = (1.f - zz) * nn + zz * sh[r][m];
            sh[r][m] = hn;
            g_concat[((size_t)(row0 + r) * Tc + tstep) * G3c + outOff + m] = hn;
        }
        __syncthreads();
    }
}

// ---------------------------------------------------------------------------
// Kernel 4: FC (384->128) + LN + relu + both heads, fused. 32 rows/block.
// ---------------------------------------------------------------------------
__global__ void k_fc(const float* __restrict__ Wfc, const float* __restrict__ bfc,
                     const float* __restrict__ lg,  const float* __restrict__ lb,
                     const float* __restrict__ Wst, const float* __restrict__ bst,
                     const float* __restrict__ Wca, const float* __restrict__ bca,
                     float* __restrict__ out)
{
    __shared__ float sA[32 * 32];
    __shared__ float sW[32 * 128];
    __shared__ float sH[32 * 128];
    __shared__ float sHW[128 * 16];
    __shared__ float sLg[128], sLb[128];

    const int row0 = blockIdx.x * 32;
    const int t    = threadIdx.x;        // 256

    for (int i = t; i < 128 * 8; i += 256) {
        int k = i >> 3, o = i & 7;
        sHW[k * 16 + o]     = Wst[i];
        sHW[k * 16 + 8 + o] = Wca[i];
    }
    if (t < 128) { sLg[t] = lg[t]; sLb[t] = lb[t]; }

    const int tc = t & 31, tr = t >> 5;
    float acc[4][4];
    #pragma unroll
    for (int b = 0; b < 4; b++) {
        float bv = bfc[tc + 32 * b];
        #pragma unroll
        for (int a = 0; a < 4; a++) acc[a][b] = bv;
    }

    for (int kt = 0; kt < 12; kt++) {
        __syncthreads();
        for (int i = t; i < 32 * 32; i += 256) {
            int r = i >> 5, k = i & 31;
            sA[i] = g_concat[(size_t)(row0 + r) * G3c + kt * 32 + k];
        }
        for (int i = t; i < 32 * 128; i += 256) {
            int k = i >> 7, c = i & 127;
            sW[i] = Wfc[(size_t)(kt * 32 + k) * 128 + c];
        }
        __syncthreads();
        #pragma unroll
        for (int k = 0; k < 32; k++) {
            float av[4], wv[4];
            #pragma unroll
            for (int a = 0; a < 4; a++) av[a] = sA[(tr + 8 * a) * 32 + k];
            #pragma unroll
            for (int b = 0; b < 4; b++) wv[b] = sW[k * 128 + tc + 32 * b];
            #pragma unroll
            for (int a = 0; a < 4; a++)
                #pragma unroll
                for (int b = 0; b < 4; b++)
                    acc[a][b] = fmaf(av[a], wv[b], acc[a][b]);
        }
    }
    __syncthreads();
    #pragma unroll
    for (int a = 0; a < 4; a++)
        #pragma unroll
        for (int b = 0; b < 4; b++)
            sH[(tr + 8 * a) * 128 + tc + 32 * b] = acc[a][b];
    __syncthreads();

    // LN(128) + relu per row
    {
        int w = t >> 5, lane = t & 31;
        for (int row = w; row < 32; row += 8) {
            float x[4]; float s = 0.f, q = 0.f;
            #pragma unroll
            for (int c = 0; c < 4; c++) {
                x[c] = sH[row * 128 + lane + 32 * c];
                s += x[c]; q += x[c] * x[c];
            }
            #pragma unroll
            for (int o = 16; o; o >>= 1) {
                s += __shfl_xor_sync(0xffffffffu, s, o);
                q += __shfl_xor_sync(0xffffffffu, q, o);
            }
            float m = s * (1.f / 128.f);
            float v = q * (1.f / 128.f) - m * m;
            float inv = rsqrtf(v + 1e-5f);
            #pragma unroll
            for (int c = 0; c < 4; c++) {
                int cc = lane + 32 * c;
                sH[row * 128 + cc] = fmaxf((x[c] - m) * inv * sLg[cc] + sLb[cc], 0.f);
            }
        }
    }
    __syncthreads();

    // heads: 32 rows x 16 outputs
    for (int idx = t; idx < 32 * 16; idx += 256) {
        int r = idx >> 4, o = idx & 15;
        float a2 = (o < 8) ? bst[o] : bca[o - 8];
        #pragma unroll 16
        for (int k = 0; k < 128; k++)
            a2 = fmaf(sH[r * 128 + k], sHW[k * 16 + o], a2);
        int row = row0 + r;
        if (o < 8) out[(size_t)row * OSTc + o] = a2;
        else       out[(size_t)BT * OSTc + (size_t)row * OSTc + (o - 8)] = a2;
    }
}

// ---------------------------------------------------------------------------
extern "C" void kernel_launch(void* const* d_in, const int* in_sizes, int n_in,
                              void* d_out, int out_size)
{
    const float* feat    = (const float*)d_in[0];
    const float* sensor  = (const float*)d_in[1];
    const float* target  = (const float*)d_in[2];
    const int*   adj     = (const int*)  d_in[3];
    const float* W_g1    = (const float*)d_in[4];
    const float* b_g1    = (const float*)d_in[5];
    const float* W_g3    = (const float*)d_in[6];
    const float* b_g3    = (const float*)d_in[7];
    const float* ln_g_g  = (const float*)d_in[8];
    const float* ln_g_b  = (const float*)d_in[9];
    const float* WiG     = (const float*)d_in[10];
    const float* WhG     = (const float*)d_in[11];
    const float* biG     = (const float*)d_in[12];
    const float* bhG     = (const float*)d_in[13];
    const float* WiS     = (const float*)d_in[14];
    const float* WhS     = (const float*)d_in[15];
    const float* biS     = (const float*)d_in[16];
    const float* bhS     = (const float*)d_in[17];
    const float* WiT     = (const float*)d_in[18];
    const float* WhT     = (const float*)d_in[19];
    const float* biT     = (const float*)d_in[20];
    const float* bhT     = (const float*)d_in[21];
    const float* W_fc1   = (const float*)d_in[22];
    const float* b_fc1   = (const float*)d_in[23];
    const float* ln_fc_g = (const float*)d_in[24];
    const float* ln_fc_b = (const float*)d_in[25];
    const float* W_st    = (const float*)d_in[26];
    const float* b_st    = (const float*)d_in[27];
    const float* W_ca    = (const float*)d_in[28];
    const float* b_ca    = (const float*)d_in[29];
    float* out = (float*)d_out;

    k_gnn<<<BT, 128>>>(feat, adj, W_g1, b_g1, W_g3, b_g3, ln_g_g, ln_g_b);
    k_xp<<<dim3(BT / 32, 3, 3), 256>>>(sensor, target, WiG, biG, WiS, biS, WiT, biT);
    k_gru<<<96, 384>>>(WhG, bhG, WhS, bhS, WhT, bhT);
    k_fc<<<BT / 32, 256>>>(W_fc1, b_fc1, ln_fc_g, ln_fc_b, W_st, b_st, W_ca, b_ca, out);
}

// round 6
// speedup vs baseline: 1.3422x; 1.3422x over previous
#include <cuda_runtime.h>

// Problem constants
constexpr int Bc   = 256;
constexpr int Tc   = 50;
constexpr int Nn   = 32;
constexpr int FINc = 16;
constexpr int HGc  = 64;
constexpr int HFCc = 128;
constexpr int G3c  = 384;           // 3*HFC
constexpr int BT   = Bc * Tc;       // 12800
constexpr int OSTc = 8;

// GRU partitioning: 6 batch rows per block -> 43 chunks per stream, 129 blocks
constexpr int GR  = 6;
constexpr int CPB = 43;

// Scratch (static __device__ globals: allocation-free rule)
__device__ float g_graph[BT * HGc];          // graph_seq (B*T, 64)
__device__ float g_agg2[BT * HGc];           // layer-2 aggregated features
__device__ float g_xp[3][BT * G3c];          // x@Wi+bi per stream
__device__ float g_concat[BT * G3c];         // [gG | gS | gT]

// ---------------------------------------------------------------------------
// Kernel 1: GNN layer 1 + aggregation for layer 2 (node 0 only).
// One block per (b,t). No W3 load here (that GEMM is batched in k_gnn2).
// ---------------------------------------------------------------------------
__global__ void k_gnn(const float* __restrict__ feat, const int* __restrict__ adj,
                      const float* __restrict__ W1, const float* __restrict__ b1,
                      const float* __restrict__ lg, const float* __restrict__ lb)
{
    __shared__ float s_feat[Nn * FINc];
    __shared__ int   s_adj[Nn * Nn];
    __shared__ float s_deg[Nn];
    __shared__ float s_agg[Nn * FINc];
    __shared__ float s_pre[Nn * HGc];
    __shared__ float s_W1[FINc * HGc];

    const int bt = blockIdx.x;
    const int t  = threadIdx.x;          // 128 threads

    for (int i = t; i < Nn * FINc; i += 128) s_feat[i] = feat[(size_t)bt * Nn * FINc + i];
    for (int i = t; i < Nn * Nn;   i += 128) s_adj[i]  = adj[(size_t)bt * Nn * Nn + i];
    for (int i = t; i < FINc * HGc; i += 128) s_W1[i]  = W1[i];
    __syncthreads();

    if (t < Nn) {                        // deg = sum(adj) + 1 (self loop)
        float s = 1.0f;
        #pragma unroll 8
        for (int j = 0; j < Nn; j++) s += (float)s_adj[t * Nn + j];
        s_deg[t] = s;
    }
    __syncthreads();

    // agg1[i][f] = (feat[i][f] + sum_j adj[i][j]*feat[j][f]) / deg[i]
    for (int idx = t; idx < Nn * FINc; idx += 128) {
        int i = idx >> 4, f = idx & 15;
        float acc = s_feat[i * FINc + f];
        #pragma unroll 8
        for (int j = 0; j < Nn; j++)
            acc += (float)s_adj[i * Nn + j] * s_feat[j * FINc + f];
        s_agg[idx] = acc / s_deg[i];
    }
    __syncthreads();

    // pre1 = agg1 @ W1 + b1
    for (int idx = t; idx < Nn * HGc; idx += 128) {
        int i = idx >> 6, h = idx & 63;
        float acc = b1[h];
        #pragma unroll
        for (int k = 0; k < FINc; k++)
            acc += s_agg[i * FINc + k] * s_W1[k * HGc + h];
        s_pre[idx] = acc;
    }
    __syncthreads();

    // LN(64) + relu per node row -> h1 (in-place)
    {
        int w = t >> 5, lane = t & 31;
        float g0 = lg[lane], g1 = lg[lane + 32];
        float c0 = lb[lane], c1 = lb[lane + 32];
        for (int row = w; row < Nn; row += 4) {
            float x0 = s_pre[row * HGc + lane];
            float x1 = s_pre[row * HGc + 32 + lane];
            float s = x0 + x1, q = x0 * x0 + x1 * x1;
            #pragma unroll
            for (int o = 16; o; o >>= 1) {
                s += __shfl_xor_sync(0xffffffffu, s, o);
                q += __shfl_xor_sync(0xffffffffu, q, o);
            }
            float m = s * (1.0f / 64.0f);
            float v = q * (1.0f / 64.0f) - m * m;
            float inv = rsqrtf(v + 1e-5f);
            s_pre[row * HGc + lane]      = fmaxf((x0 - m) * inv * g0 + c0, 0.f);
            s_pre[row * HGc + 32 + lane] = fmaxf((x1 - m) * inv * g1 + c1, 0.f);
        }
    }
    __syncthreads();

    // layer 2 aggregation, row 0 only -> global (GEMM done in k_gnn2)
    if (t < HGc) {
        float acc = s_pre[t];            // identity j==0
        #pragma unroll 8
        for (int j = 0; j < Nn; j++)
            acc += (float)s_adj[j] * s_pre[j * HGc + t];
        g_agg2[(size_t)bt * HGc + t] = acc / s_deg[0];
    }
}

// ---------------------------------------------------------------------------
// Kernel 1b: batched layer-2 GEMM (12800 x 64 @ 64 x 64) + LN + relu -> g_graph
// 32 rows per block, 256 threads.
// ---------------------------------------------------------------------------
__global__ void k_gnn2(const float* __restrict__ W3, const float* __restrict__ b3,
                       const float* __restrict__ lg, const float* __restrict__ lb)
{
    __shared__ float sW[HGc * HGc];      // 16KB
    __shared__ float sA[32 * HGc];       // 8KB
    __shared__ float sP[32 * HGc];       // 8KB

    const int row0 = blockIdx.x * 32;
    const int t    = threadIdx.x;        // 256

    for (int i = t; i < HGc * HGc; i += 256) sW[i] = W3[i];
    for (int i = t; i < 32 * HGc; i += 256)  sA[i] = g_agg2[(size_t)row0 * HGc + i];
    __syncthreads();

    for (int idx = t; idx < 32 * HGc; idx += 256) {
        int r = idx >> 6, h = idx & 63;
        float acc = b3[h];
        #pragma unroll 16
        for (int k = 0; k < HGc; k++)
            acc += sA[r * HGc + k] * sW[k * HGc + h];
        sP[idx] = acc;
    }
    __syncthreads();

    // LN(64) + relu per row
    {
        int w = t >> 5, lane = t & 31;
        float g0 = lg[lane], g1 = lg[lane + 32];
        float c0 = lb[lane], c1 = lb[lane + 32];
        for (int row = w; row < 32; row += 8) {
            float x0 = sP[row * HGc + lane];
            float x1 = sP[row * HGc + 32 + lane];
            float s = x0 + x1, q = x0 * x0 + x1 * x1;
            #pragma unroll
            for (int o = 16; o; o >>= 1) {
                s += __shfl_xor_sync(0xffffffffu, s, o);
                q += __shfl_xor_sync(0xffffffffu, q, o);
            }
            float m = s * (1.f / 64.f);
            float v = q * (1.f / 64.f) - m * m;
            float inv = rsqrtf(v + 1e-5f);
            g_graph[(size_t)(row0 + row) * HGc + lane]      = fmaxf((x0 - m) * inv * g0 + c0, 0.f);
            g_graph[(size_t)(row0 + row) * HGc + 32 + lane] = fmaxf((x1 - m) * inv * g1 + c1, 0.f);
        }
    }
}

// ---------------------------------------------------------------------------
// Kernel 2: xp = x @ Wi + bi for the three GRU streams (tiled GEMM)
// ---------------------------------------------------------------------------
__global__ void k_xp(const float* __restrict__ sensor, const float* __restrict__ target,
                     const float* __restrict__ WiG, const float* __restrict__ biG,
                     const float* __restrict__ WiS, const float* __restrict__ biS,
                     const float* __restrict__ WiT, const float* __restrict__ biT)
{
    __shared__ float sA[32 * 64];
    __shared__ float sW[64 * 128];

    const int s    = blockIdx.z;
    const int col0 = blockIdx.y * 128;
    const int row0 = blockIdx.x * 32;
    const int t    = threadIdx.x;        // 256

    const float* A; const float* Wi; const float* bi; int K;
    if (s == 0)      { A = g_graph; Wi = WiG; bi = biG; K = 64; }
    else if (s == 1) { A = sensor;  Wi = WiS; bi = biS; K = 32; }
    else             { A = target;  Wi = WiT; bi = biT; K = 32; }

    for (int i = t; i < 32 * K; i += 256) {
        int r = i / K, k = i % K;
        sA[r * K + k] = A[(size_t)(row0 + r) * K + k];
    }
    for (int i = t; i < K * 128; i += 256) {
        int k = i >> 7, c = i & 127;
        sW[i] = Wi[(size_t)k * G3c + col0 + c];
    }
    __syncthreads();

    const int tc = t & 31, tr = t >> 5;  // 8 row-threads x 32 col-threads
    float acc[4][4];
    #pragma unroll
    for (int b = 0; b < 4; b++) {
        float bv = bi[col0 + tc + 32 * b];
        #pragma unroll
        for (int a = 0; a < 4; a++) acc[a][b] = bv;
    }
    for (int k = 0; k < K; k++) {
        float av[4], wv[4];
        #pragma unroll
        for (int a = 0; a < 4; a++) av[a] = sA[(tr + 8 * a) * K + k];
        #pragma unroll
        for (int b = 0; b < 4; b++) wv[b] = sW[k * 128 + tc + 32 * b];
        #pragma unroll
        for (int a = 0; a < 4; a++)
            #pragma unroll
            for (int b = 0; b < 4; b++)
                acc[a][b] = fmaf(av[a], wv[b], acc[a][b]);
    }
    float* Xp = g_xp[s];
    #pragma unroll
    for (int a = 0; a < 4; a++)
        #pragma unroll
        for (int b = 0; b < 4; b++)
            Xp[(size_t)(row0 + tr + 8 * a) * G3c + col0 + tc + 32 * b] = acc[a][b];
}

// ---------------------------------------------------------------------------
// Kernel 3: persistent GRU recurrence. 129 blocks (3 streams x 43 chunks of 6
// batch rows), 384 threads; thread j owns gh column j with its Wh column packed
// in 64 f32x2 registers (fma.rn.f32x2 = 2 MACs/instr).
// Row-streamed (no ghv[] array) to stay under the 170-reg cap -> no spills.
// ---------------------------------------------------------------------------
__device__ __forceinline__ unsigned long long pk2(float lo, float hi) {
    unsigned long long r;
    asm("mov.b64 %0, {%1,%2};" : "=l"(r) : "f"(lo), "f"(hi));
    return r;
}
__device__ __forceinline__ unsigned long long ffma2(unsigned long long a,
                                                    unsigned long long b,
                                                    unsigned long long c) {
    unsigned long long d;
    asm("fma.rn.f32x2 %0, %1, %2, %3;" : "=l"(d) : "l"(a), "l"(b), "l"(c));
    return d;
}
__device__ __forceinline__ float f2red(unsigned long long a) {
    float lo, hi;
    asm("mov.b64 {%0,%1}, %2;" : "=f"(lo), "=f"(hi) : "l"(a));
    return lo + hi;
}

__global__ void __launch_bounds__(384, 1)
k_gru(const float* __restrict__ WhG, const float* __restrict__ bhG,
      const float* __restrict__ WhS, const float* __restrict__ bhS,
      const float* __restrict__ WhT, const float* __restrict__ bhT)
{
    __shared__ __align__(16) float sh[GR][128];  // hidden state, GR batch rows
    __shared__ float sAg[GR][384];               // pre_r | pre_z | hg
    __shared__ float sIG[GR][128];               // ig (input part of n gate)

    const int bx     = blockIdx.x;
    const int stream = bx / CPB;                 // 0..2
    const int row0   = (bx % CPB) * GR;          // batch rows [row0, row0+GR)
    const int j      = threadIdx.x;              // 0..383 column owner

    const float* Wh; const float* bh;
    if (stream == 0)      { Wh = WhG; bh = bhG; }
    else if (stream == 1) { Wh = WhS; bh = bhS; }
    else                  { Wh = WhT; bh = bhT; }
    const float* Xp     = g_xp[stream];
    const int    outOff = stream * 128;

    // Preload this thread's Wh column as 64 packed f32x2 registers (128 regs)
    unsigned long long whp[64];
    #pragma unroll
    for (int kk = 0; kk < 64; kk++) {
        float lo = Wh[(size_t)(2 * kk) * G3c + j];
        float hi = Wh[(size_t)(2 * kk + 1) * G3c + j];
        whp[kk] = pk2(lo, hi);
    }
    const float bhj = bh[j];

    #pragma unroll
    for (int i = j; i < GR * 128; i += 384) sh[i >> 7][i & 127] = 0.f;
    __syncthreads();

    for (int tstep = 0; tstep < Tc; tstep++) {
        float xv[GR];
        #pragma unroll
        for (int r = 0; r < GR; r++) {
            int row = row0 + r;
            xv[r] = (row < Bc) ? Xp[((size_t)row * Tc + tstep) * G3c + j] : 0.f;
        }

        // Row-streamed gh: compute and immediately store (keeps regs < 170)
        #pragma unroll
        for (int r = 0; r < GR; r++) {
            unsigned long long a0 = 0ull, a1 = 0ull;
            #pragma unroll
            for (int q = 0; q < 32; q++) {
                ulonglong2 hv = *reinterpret_cast<const ulonglong2*>(&sh[r][4 * q]);
                a0 = ffma2(hv.x, whp[2 * q],     a0);
                a1 = ffma2(hv.y, whp[2 * q + 1], a1);
            }
            float gh = f2red(a0) + f2red(a1) + bhj;
            if (j < 256) {
                sAg[r][j] = xv[r] + gh;              // pre_r / pre_z
            } else {
                sAg[r][j] = gh;                      // hg
                sIG[r][j - 256] = xv[r];             // ig
            }
        }
        __syncthreads();

        // gate math: GR*128 (row, unit) pairs over 384 threads (exactly 2 iters)
        #pragma unroll
        for (int it = 0; it < (GR * 128) / 384; it++) {
            int u = j + it * 384;
            int r = u >> 7, m = u & 127;
            float pr = sAg[r][m];
            float pz = sAg[r][128 + m];
            float hg = sAg[r][256 + m];
            float ig = sIG[r][m];
            float rr = 1.f / (1.f + __expf(-pr));
            float zz = 1.f / (1.f + __expf(-pz));
            float nn = tanhf(fmaf(rr, hg, ig));
            float hn = (1.f - zz) * nn + zz * sh[r][m];
            sh[r][m] = hn;
            int row = row0 + r;
            if (row < Bc)
                g_concat[((size_t)row * Tc + tstep) * G3c + outOff + m] = hn;
        }
        __syncthreads();
    }
}

// ---------------------------------------------------------------------------
// Kernel 4: FC (384->128) + LN + relu + both heads, fused. 32 rows/block.
// ---------------------------------------------------------------------------
__global__ void k_fc(const float* __restrict__ Wfc, const float* __restrict__ bfc,
                     const float* __restrict__ lg,  const float* __restrict__ lb,
                     const float* __restrict__ Wst, const float* __restrict__ bst,
                     const float* __restrict__ Wca, const float* __restrict__ bca,
                     float* __restrict__ out)
{
    __shared__ float sA[32 * 32];
    __shared__ float sW[32 * 128];
    __shared__ float sH[32 * 128];
    __shared__ float sHW[128 * 16];
    __shared__ float sLg[128], sLb[128];

    const int row0 = blockIdx.x * 32;
    const int t    = threadIdx.x;        // 256

    for (int i = t; i < 128 * 8; i += 256) {
        int k = i >> 3, o = i & 7;
        sHW[k * 16 + o]     = Wst[i];
        sHW[k * 16 + 8 + o] = Wca[i];
    }
    if (t < 128) { sLg[t] = lg[t]; sLb[t] = lb[t]; }

    const int tc = t & 31, tr = t >> 5;
    float acc[4][4];
    #pragma unroll
    for (int b = 0; b < 4; b++) {
        float bv = bfc[tc + 32 * b];
        #pragma unroll
        for (int a = 0; a < 4; a++) acc[a][b] = bv;
    }

    for (int kt = 0; kt < 12; kt++) {
        __syncthreads();
        for (int i = t; i < 32 * 32; i += 256) {
            int r = i >> 5, k = i & 31;
            sA[i] = g_concat[(size_t)(row0 + r) * G3c + kt * 32 + k];
        }
        for (int i = t; i < 32 * 128; i += 256) {
            int k = i >> 7, c = i & 127;
            sW[i] = Wfc[(size_t)(kt * 32 + k) * 128 + c];
        }
        __syncthreads();
        #pragma unroll
        for (int k = 0; k < 32; k++) {
            float av[4], wv[4];
            #pragma unroll
            for (int a = 0; a < 4; a++) av[a] = sA[(tr + 8 * a) * 32 + k];
            #pragma unroll
            for (int b = 0; b < 4; b++) wv[b] = sW[k * 128 + tc + 32 * b];
            #pragma unroll
            for (int a = 0; a < 4; a++)
                #pragma unroll
                for (int b = 0; b < 4; b++)
                    acc[a][b] = fmaf(av[a], wv[b], acc[a][b]);
        }
    }
    __syncthreads();
    #pragma unroll
    for (int a = 0; a < 4; a++)
        #pragma unroll
        for (int b = 0; b < 4; b++)
            sH[(tr + 8 * a) * 128 + tc + 32 * b] = acc[a][b];
    __syncthreads();

    // LN(128) + relu per row
    {
        int w = t >> 5, lane = t & 31;
        for (int row = w; row < 32; row += 8) {
            float x[4]; float s = 0.f, q = 0.f;
            #pragma unroll
            for (int c = 0; c < 4; c++) {
                x[c] = sH[row * 128 + lane + 32 * c];
                s += x[c]; q += x[c] * x[c];
            }
            #pragma unroll
            for (int o = 16; o; o >>= 1) {
                s += __shfl_xor_sync(0xffffffffu, s, o);
                q += __shfl_xor_sync(0xffffffffu, q, o);
            }
            float m = s * (1.f / 128.f);
            float v = q * (1.f / 128.f) - m * m;
            float inv = rsqrtf(v + 1e-5f);
            #pragma unroll
            for (int c = 0; c < 4; c++) {
                int cc = lane + 32 * c;
                sH[row * 128 + cc] = fmaxf((x[c] - m) * inv * sLg[cc] + sLb[cc], 0.f);
            }
        }
    }
    __syncthreads();

    // heads: 32 rows x 16 outputs
    for (int idx = t; idx < 32 * 16; idx += 256) {
        int r = idx >> 4, o = idx & 15;
        float a2 = (o < 8) ? bst[o] : bca[o - 8];
        #pragma unroll 16
        for (int k = 0; k < 128; k++)
            a2 = fmaf(sH[r * 128 + k], sHW[k * 16 + o], a2);
        int row = row0 + r;
        if (o < 8) out[(size_t)row * OSTc + o] = a2;
        else       out[(size_t)BT * OSTc + (size_t)row * OSTc + (o - 8)] = a2;
    }
}

// ---------------------------------------------------------------------------
extern "C" void kernel_launch(void* const* d_in, const int* in_sizes, int n_in,
                              void* d_out, int out_size)
{
    const float* feat    = (const float*)d_in[0];
    const float* sensor  = (const float*)d_in[1];
    const float* target  = (const float*)d_in[2];
    const int*   adj     = (const int*)  d_in[3];
    const float* W_g1    = (const float*)d_in[4];
    const float* b_g1    = (const float*)d_in[5];
    const float* W_g3    = (const float*)d_in[6];
    const float* b_g3    = (const float*)d_in[7];
    const float* ln_g_g  = (const float*)d_in[8];
    const float* ln_g_b  = (const float*)d_in[9];
    const float* WiG     = (const float*)d_in[10];
    const float* WhG     = (const float*)d_in[11];
    const float* biG     = (const float*)d_in[12];
    const float* bhG     = (const float*)d_in[13];
    const float* WiS     = (const float*)d_in[14];
    const float* WhS     = (const float*)d_in[15];
    const float* biS     = (const float*)d_in[16];
    const float* bhS     = (const float*)d_in[17];
    const float* WiT     = (const float*)d_in[18];
    const float* WhT     = (const float*)d_in[19];
    const float* biT     = (const float*)d_in[20];
    const float* bhT     = (const float*)d_in[21];
    const float* W_fc1   = (const float*)d_in[22];
    const float* b_fc1   = (const float*)d_in[23];
    const float* ln_fc_g = (const float*)d_in[24];
    const float* ln_fc_b = (const float*)d_in[25];
    const float* W_st    = (const float*)d_in[26];
    const float* b_st    = (const float*)d_in[27];
    const float* W_ca    = (const float*)d_in[28];
    const float* b_ca    = (const float*)d_in[29];
    float* out = (float*)d_out;

    k_gnn<<<BT, 128>>>(feat, adj, W_g1, b_g1, ln_g_g, ln_g_b);
    k_gnn2<<<BT / 32, 256>>>(W_g3, b_g3, ln_g_g, ln_g_b);
    k_xp<<<dim3(BT / 32, 3, 3), 256>>>(sensor, target, WiG, biG, WiS, biS, WiT, biT);
    k_gru<<<3 * CPB, 384>>>(WhG, bhG, WhS, bhS, WhT, bhT);
    k_fc<<<BT / 32, 256>>>(W_fc1, b_fc1, ln_fc_g, ln_fc_b, W_st, b_st, W_ca, b_ca, out);
}